// round 7
// baseline (speedup 1.0000x reference)
#include <cuda_runtime.h>
#include <cuda_bf16.h>
#include <math.h>
#include <stdint.h>

#define L_SEQ  4096
#define NB     2
#define BLTOK  8192
#define DM     768
#define DI     1536
#define DS     16
#define DTR    48
#define NLAYER 4

// ---------------- scratch (static device globals) ----------------
__device__ float g_h    [BLTOK * DM];
__device__ float g_res  [BLTOK * DM];
__device__ float g_xz   [2 * DI * BLTOK];   // rows [0,DI): x ; [DI,2DI): z  (channel, token)
__device__ float g_xconv[DI * BLTOK];
__device__ float g_dt   [DTR * BLTOK];
__device__ float g_BcT  [BLTOK * DS];
__device__ float g_CcT  [BLTOK * DS];
__device__ float g_delta[DI * BLTOK];
__device__ float g_y    [DI * BLTOK];       // (channel, token)

__device__ __nv_bfloat16 g_WinHi[2 * DI * DM], g_WinLo[2 * DI * DM];
__device__ __nv_bfloat16 g_WoutHi[DM * DI],   g_WoutLo[DM * DI];
__device__ __nv_bfloat16 g_hnHi[BLTOK * DM],  g_hnLo[BLTOK * DM];   // token-major
__device__ __nv_bfloat16 g_yHi[BLTOK * DI],   g_yLo[BLTOK * DI];    // token-major

// ---------------- helpers ----------------
__device__ __forceinline__ uint32_t smem_u32(const void* p) {
    uint32_t a;
    asm("{ .reg .u64 t; cvta.to.shared.u64 t, %1; cvt.u32.u64 %0, t; }" : "=r"(a) : "l"(p));
    return a;
}
#define LDSM_X4(r0, r1, r2, r3, a) \
    asm volatile("ldmatrix.sync.aligned.m8n8.x4.shared.b16 {%0,%1,%2,%3}, [%4];" \
                 : "=r"(r0), "=r"(r1), "=r"(r2), "=r"(r3) : "r"(a))
#define MMA_BF16(c, a0, a1, a2, a3, b0, b1) \
    asm volatile("mma.sync.aligned.m16n8k16.row.col.f32.bf16.bf16.f32 " \
                 "{%0,%1,%2,%3}, {%4,%5,%6,%7}, {%8,%9}, {%0,%1,%2,%3};" \
                 : "+f"((c)[0]), "+f"((c)[1]), "+f"((c)[2]), "+f"((c)[3]) \
                 : "r"(a0), "r"(a1), "r"(a2), "r"(a3), "r"(b0), "r"(b1))
#define CP_A16(dst, src) \
    asm volatile("cp.async.cg.shared.global [%0], [%1], 16;" :: "r"(dst), "l"(src))
#define CP_COMMIT()  asm volatile("cp.async.commit_group;")
#define CP_WAIT(n)   asm volatile("cp.async.wait_group %0;" :: "n"(n))

// ---------------- mma.sync 3xBF16 GEMM: C = A(MxK) * B(NtokxK)^T ----------------
// LAYOUT 0: C[(bm+m)*ldc + bn+n]   LAYOUT 1: C[(bn+n)*ldc + bm+m]
// smem per stage: 4 tiles (Ah, Al, Bh, Bl), each 128 rows x 32 bf16, stride 80 B
#define TILE_B  10240              // 128*80
#define STAGE_B 40960              // 4 tiles
#define EPI_STRIDE 130             // floats
#define MMASMEM 81920              // 2 stages (>= epi staging 66560)

template <int LAYOUT>
__device__ __forceinline__ void mma_gemm_body(
    char* dsm,
    const __nv_bfloat16* __restrict__ Ahi, const __nv_bfloat16* __restrict__ Alo,
    const __nv_bfloat16* __restrict__ Bhi, const __nv_bfloat16* __restrict__ Blo,
    float* __restrict__ C, int K, int ldc) {
    const int tid = threadIdx.x;
    const int wid = tid >> 5;
    const int lane = tid & 31;
    const int bm = blockIdx.y * 128;
    const int bn = blockIdx.x * 128;
    const int wm = (wid >> 2) * 64;
    const int wn = (wid & 3) * 32;

    const uint32_t sb = smem_u32(dsm);

    // cp.async map: per thread, 2 x 16B per tile (128 rows x 64B = 512 vectors)
    uint32_t so[2];
    size_t offA[2], offB[2];
#pragma unroll
    for (int j = 0; j < 2; j++) {
        int v = tid + j * 256;
        int row = v >> 2, c = v & 3;
        so[j] = row * 80 + c * 16;
        offA[j] = (size_t)(bm + row) * K + c * 8;
        offB[j] = (size_t)(bn + row) * K + c * 8;
    }

    // ldmatrix lane-address offsets (bytes within a tile)
    uint32_t aoff[4], boff[2];
    {
        int g = lane >> 3, r = lane & 7;
#pragma unroll
        for (int mt = 0; mt < 4; mt++) {
            int row = wm + mt * 16 + (g & 1) * 8 + r;
            aoff[mt] = row * 80 + (g >> 1) * 16;
        }
#pragma unroll
        for (int p = 0; p < 2; p++) {
            int row = wn + p * 16 + (g >> 1) * 8 + r;
            boff[p] = row * 80 + (g & 1) * 16;
        }
    }

    const int KT = K >> 5;   // BK = 32

    auto issue = [&](int kc, int stg) {
        int k0 = kc << 5;
        uint32_t base = sb + stg * STAGE_B;
#pragma unroll
        for (int j = 0; j < 2; j++) {
            uint32_t d = base + so[j];
            CP_A16(d,              Ahi + offA[j] + k0);
            CP_A16(d + TILE_B,     Alo + offA[j] + k0);
            CP_A16(d + 2 * TILE_B, Bhi + offB[j] + k0);
            CP_A16(d + 3 * TILE_B, Blo + offB[j] + k0);
        }
        CP_COMMIT();
    };

    float acc[4][4][4];
#pragma unroll
    for (int mt = 0; mt < 4; mt++)
#pragma unroll
        for (int nt = 0; nt < 4; nt++)
#pragma unroll
            for (int e = 0; e < 4; e++) acc[mt][nt][e] = 0.f;

    issue(0, 0);
    if (KT > 1) issue(1, 1);

    for (int kc = 0; kc < KT; kc++) {
        if (kc + 1 < KT) CP_WAIT(1); else CP_WAIT(0);
        __syncthreads();
        uint32_t base = sb + (kc & 1) * STAGE_B;
        uint32_t sAh = base, sAl = base + TILE_B, sBh = base + 2 * TILE_B, sBl = base + 3 * TILE_B;
#pragma unroll
        for (int ks = 0; ks < 2; ks++) {
            uint32_t kb = ks * 32;
            // B fragments first (16 regs live)
            uint32_t bh[2][4], bl[2][4];
#pragma unroll
            for (int p = 0; p < 2; p++) {
                LDSM_X4(bh[p][0], bh[p][1], bh[p][2], bh[p][3], sBh + boff[p] + kb);
                LDSM_X4(bl[p][0], bl[p][1], bl[p][2], bl[p][3], sBl + boff[p] + kb);
            }
            // A fragments per-mt (8 regs live at a time) -> no spills at 128-reg cap
#pragma unroll
            for (int mt = 0; mt < 4; mt++) {
                uint32_t ah[4], al[4];
                LDSM_X4(ah[0], ah[1], ah[2], ah[3], sAh + aoff[mt] + kb);
                LDSM_X4(al[0], al[1], al[2], al[3], sAl + aoff[mt] + kb);
#pragma unroll
                for (int nt = 0; nt < 4; nt++) {
                    int p = nt >> 1, h = (nt & 1) * 2;
                    MMA_BF16(acc[mt][nt], ah[0], ah[1], ah[2], ah[3], bh[p][h], bh[p][h + 1]);
                    MMA_BF16(acc[mt][nt], ah[0], ah[1], ah[2], ah[3], bl[p][h], bl[p][h + 1]);
                    MMA_BF16(acc[mt][nt], al[0], al[1], al[2], al[3], bh[p][h], bh[p][h + 1]);
                }
            }
        }
        __syncthreads();
        if (kc + 2 < KT) issue(kc + 2, kc & 1);
    }

    // epilogue: accum -> smem staging (float, stride 130) -> coalesced GMEM
    float* st = (float*)dsm;
    {
        int mr = lane >> 2;
        int nc = (lane & 3) * 2;
#pragma unroll
        for (int mt = 0; mt < 4; mt++) {
#pragma unroll
            for (int nt = 0; nt < 4; nt++) {
                int m0 = wm + mt * 16 + mr;
                int n0 = wn + nt * 8 + nc;
                *(float2*)(st + m0 * EPI_STRIDE + n0) = make_float2(acc[mt][nt][0], acc[mt][nt][1]);
                *(float2*)(st + (m0 + 8) * EPI_STRIDE + n0) = make_float2(acc[mt][nt][2], acc[mt][nt][3]);
            }
        }
    }
    __syncthreads();
    if (LAYOUT == 0) {
        for (int idx = tid; idx < 16384; idx += 256) {
            int r = idx >> 7, c = idx & 127;
            C[(size_t)(bm + r) * ldc + bn + c] = st[r * EPI_STRIDE + c];
        }
    } else {
        for (int idx = tid; idx < 16384; idx += 256) {
            int n = idx >> 7, m = idx & 127;
            C[(size_t)(bn + n) * ldc + bm + m] = st[m * EPI_STRIDE + n];
        }
    }
}

__global__ void __launch_bounds__(256, 2) mma_gemm_a(
    const __nv_bfloat16* __restrict__ Ahi, const __nv_bfloat16* __restrict__ Alo,
    const __nv_bfloat16* __restrict__ Bhi, const __nv_bfloat16* __restrict__ Blo,
    float* __restrict__ C, int K, int ldc) {
    extern __shared__ char dsm[];
    mma_gemm_body<0>(dsm, Ahi, Alo, Bhi, Blo, C, K, ldc);
}
__global__ void __launch_bounds__(256, 2) mma_gemm_b(
    const __nv_bfloat16* __restrict__ Ahi, const __nv_bfloat16* __restrict__ Alo,
    const __nv_bfloat16* __restrict__ Bhi, const __nv_bfloat16* __restrict__ Blo,
    float* __restrict__ C, int K, int ldc) {
    extern __shared__ char dsm[];
    mma_gemm_body<1>(dsm, Ahi, Alo, Bhi, Blo, C, K, ldc);
}

// ---------------- fp32 -> bf16 hi/lo elementwise ----------------
__global__ void cvt_pair_kernel(const float* __restrict__ src, __nv_bfloat16* __restrict__ hi,
                                __nv_bfloat16* __restrict__ lo, int n) {
    int i = blockIdx.x * 256 + threadIdx.x;
    if (i < n) {
        float v = src[i];
        __nv_bfloat16 h = __float2bfloat16(v);
        hi[i] = h;
        lo[i] = __float2bfloat16(v - __bfloat162float(h));
    }
}

// ---------------- transpose (d,tok)->(tok,d) + bf16 hi/lo ----------------
__global__ void tcvt_kernel(const float* __restrict__ src, __nv_bfloat16* __restrict__ hi,
                            __nv_bfloat16* __restrict__ lo) {
    __shared__ float t[32][33];
    int tx = threadIdx.x & 31, ty = threadIdx.x >> 5;
    int tok0 = blockIdx.x * 32, d0 = blockIdx.y * 32;
#pragma unroll
    for (int i = 0; i < 4; i++) {
        int d = d0 + ty + i * 8;
        t[ty + i * 8][tx] = src[(size_t)d * BLTOK + tok0 + tx];
    }
    __syncthreads();
#pragma unroll
    for (int i = 0; i < 4; i++) {
        int tok = tok0 + ty + i * 8;
        float v = t[tx][ty + i * 8];
        __nv_bfloat16 h = __float2bfloat16(v);
        size_t o = (size_t)tok * DI + d0 + tx;
        hi[o] = h;
        lo[o] = __float2bfloat16(v - __bfloat162float(h));
    }
}

// ---------------- embed ----------------
__global__ void embed_kernel(const float* __restrict__ x, const float* __restrict__ W,
                             const float* __restrict__ bias) {
    __shared__ float xs[64];
    int tok = blockIdx.x;
    int b = tok >> 12, l = tok & 4095;
    int tid = threadIdx.x;
    if (tid < 64) xs[tid] = x[(b * 64 + tid) * L_SEQ + l];
    __syncthreads();
    for (int e = tid; e < DM; e += 256) {
        const float* w = W + e * 64;
        float acc = bias[e];
#pragma unroll 16
        for (int i = 0; i < 64; i++) acc = fmaf(w[i], xs[i], acc);
        g_h[tok * DM + e] = acc;
    }
}

// ---------------- fused residual + layernorm (+ bf16 hi/lo out) ----------------
__global__ void resln_kernel(const float* __restrict__ src, float* __restrict__ res,
                             float* __restrict__ outf, __nv_bfloat16* __restrict__ ohi,
                             __nv_bfloat16* __restrict__ olo,
                             const float* __restrict__ w, const float* __restrict__ b, int add) {
    __shared__ float red1[8], red2[8];
    int base = blockIdx.x * DM;
    int tid = threadIdx.x;
    float v0 = src[base + tid];
    float v1 = src[base + tid + 256];
    float v2 = src[base + tid + 512];
    if (add) {
        v0 += res[base + tid];
        v1 += res[base + tid + 256];
        v2 += res[base + tid + 512];
    }
    res[base + tid]       = v0;
    res[base + tid + 256] = v1;
    res[base + tid + 512] = v2;

    float s = v0 + v1 + v2;
#pragma unroll
    for (int o = 16; o; o >>= 1) s += __shfl_xor_sync(0xffffffffu, s, o);
    if ((tid & 31) == 0) red1[tid >> 5] = s;
    __syncthreads();
    float tot = 0.f;
#pragma unroll
    for (int i = 0; i < 8; i++) tot += red1[i];
    float mean = tot * (1.f / DM);

    float d0 = v0 - mean, d1 = v1 - mean, d2 = v2 - mean;
    float sq = d0 * d0 + d1 * d1 + d2 * d2;
#pragma unroll
    for (int o = 16; o; o >>= 1) sq += __shfl_xor_sync(0xffffffffu, sq, o);
    if ((tid & 31) == 0) red2[tid >> 5] = sq;
    __syncthreads();
    float vt = 0.f;
#pragma unroll
    for (int i = 0; i < 8; i++) vt += red2[i];
    float inv = rsqrtf(vt * (1.f / DM) + 1e-5f);

    float o0 = d0 * inv * w[tid]       + b[tid];
    float o1 = d1 * inv * w[tid + 256] + b[tid + 256];
    float o2 = d2 * inv * w[tid + 512] + b[tid + 512];
    if (outf) {
        outf[base + tid]       = o0;
        outf[base + tid + 256] = o1;
        outf[base + tid + 512] = o2;
    } else {
        __nv_bfloat16 h0 = __float2bfloat16(o0), h1 = __float2bfloat16(o1), h2 = __float2bfloat16(o2);
        ohi[base + tid]       = h0;  olo[base + tid]       = __float2bfloat16(o0 - __bfloat162float(h0));
        ohi[base + tid + 256] = h1;  olo[base + tid + 256] = __float2bfloat16(o1 - __bfloat162float(h1));
        ohi[base + tid + 512] = h2;  olo[base + tid + 512] = __float2bfloat16(o2 - __bfloat162float(h2));
    }
}

// ---------------- SIMT SGEMM (x_proj / dt_proj) ----------------
#define BK 16
#define SPAD 4
enum { EPI_STORE = 0, EPI_SOFTPLUS = 1, EPI_TRANS = 2, EPI_XPROJ = 3 };

template <int BM, int BN, int TM, int TN, bool BNT, int EPI>
__device__ __forceinline__ void sgemm_body(
    const float* __restrict__ A, const float* __restrict__ B, float* __restrict__ C,
    int M, int N, int K, const float* __restrict__ bias,
    float* __restrict__ aux1, float* __restrict__ aux2) {
    constexpr int AE = BM * BK / 256;
    constexpr int BE = BN * BK / 256;
    __shared__ float As[BK][BM + SPAD];
    __shared__ float Bs[BK][BN + SPAD];

    int tid = threadIdx.x;
    int bm = blockIdx.y * BM;
    int bn = blockIdx.x * BN;
    int tx = tid % (BN / TN);
    int ty = tid / (BN / TN);

    float acc[TM][TN];
#pragma unroll
    for (int i = 0; i < TM; i++)
#pragma unroll
        for (int j = 0; j < TN; j++) acc[i][j] = 0.f;

    float pa[AE], pb[BE];
    auto loadA = [&](int k0) {
#pragma unroll
        for (int e = 0; e < AE; e++) {
            int i = tid + e * 256;
            int r = i / BK, kk = i % BK;
            int m = bm + r;
            pa[e] = (m < M) ? A[(long)m * K + k0 + kk] : 0.f;
        }
    };
    auto loadB = [&](int k0) {
#pragma unroll
        for (int e = 0; e < BE; e++) {
            int i = tid + e * 256;
            if (BNT) {
                int r = i / BK, kk = i % BK;
                pb[e] = B[(long)(bn + r) * K + k0 + kk];
            } else {
                int kk = i / BN, c = i % BN;
                pb[e] = B[(long)(k0 + kk) * N + bn + c];
            }
        }
    };
    auto storeAB = [&]() {
#pragma unroll
        for (int e = 0; e < AE; e++) {
            int i = tid + e * 256;
            As[i % BK][i / BK] = pa[e];
        }
#pragma unroll
        for (int e = 0; e < BE; e++) {
            int i = tid + e * 256;
            if (BNT) Bs[i % BK][i / BK] = pb[e];
            else     Bs[i / BN][i % BN] = pb[e];
        }
    };

    int KT = K / BK;
    loadA(0); loadB(0);
    storeAB();
    __syncthreads();

    for (int kt = 0; kt < KT; kt++) {
        if (kt + 1 < KT) { loadA((kt + 1) * BK); loadB((kt + 1) * BK); }
#pragma unroll
        for (int kk = 0; kk < BK; kk++) {
            float a[TM], bf[TN];
#pragma unroll
            for (int i = 0; i < TM; i++) a[i] = As[kk][ty * TM + i];
#pragma unroll
            for (int j = 0; j < TN; j++) bf[j] = Bs[kk][tx * TN + j];
#pragma unroll
            for (int i = 0; i < TM; i++)
#pragma unroll
                for (int j = 0; j < TN; j++) acc[i][j] = fmaf(a[i], bf[j], acc[i][j]);
        }
        __syncthreads();
        if (kt + 1 < KT) {
            storeAB();
            __syncthreads();
        }
    }

#pragma unroll
    for (int i = 0; i < TM; i++) {
        int m = bm + ty * TM + i;
        if (m >= M) continue;
#pragma unroll
        for (int j = 0; j < TN; j++) {
            int n = bn + tx * TN + j;
            float v = acc[i][j];
            if (EPI == EPI_STORE) {
                C[(long)m * N + n] = v;
            } else if (EPI == EPI_SOFTPLUS) {
                v += bias[m];
                C[(long)m * N + n] = (v > 20.f) ? v : log1pf(expf(v));
            } else if (EPI == EPI_TRANS) {
                C[(long)n * M + m] = v;
            } else {
                if (m < DTR)            C[(long)m * N + n] = v;
                else if (m < DTR + DS)  aux1[(long)n * DS + (m - DTR)] = v;
                else                    aux2[(long)n * DS + (m - DTR - DS)] = v;
            }
        }
    }
}

__global__ void __launch_bounds__(256, 2) sgemm_xproj(
    const float* __restrict__ A, const float* __restrict__ B, float* __restrict__ C,
    int M, int N, int K, float* __restrict__ aux1, float* __restrict__ aux2) {
    sgemm_body<32, 128, 2, 8, false, EPI_XPROJ>(A, B, C, M, N, K, nullptr, aux1, aux2);
}
__global__ void __launch_bounds__(256, 2) sgemm_dtproj(
    const float* __restrict__ A, const float* __restrict__ B, float* __restrict__ C,
    int M, int N, int K, const float* __restrict__ bias) {
    sgemm_body<128, 128, 8, 8, false, EPI_SOFTPLUS>(A, B, C, M, N, K, bias, nullptr, nullptr);
}

// ---------------- depthwise causal conv1d + bias + SiLU ----------------
__global__ void conv_silu_kernel(const float* __restrict__ cw, const float* __restrict__ cb) {
    int idx = blockIdx.x * 256 + threadIdx.x;
    if (idx >= DI * BLTOK) return;
    int d = idx >> 13;
    int bl = idx & 8191;
    int l = bl & 4095;
    const float* xp = g_xz + (long)d * BLTOK + bl;
    float w0 = cw[d * 4], w1 = cw[d * 4 + 1], w2 = cw[d * 4 + 2], w3 = cw[d * 4 + 3];
    float acc = cb[d];
    if (l >= 3) acc = fmaf(w0, xp[-3], acc);
    if (l >= 2) acc = fmaf(w1, xp[-2], acc);
    if (l >= 1) acc = fmaf(w2, xp[-1], acc);
    acc = fmaf(w3, xp[0], acc);
    float sg = 1.f / (1.f + __expf(-acc));
    g_xconv[idx] = acc * sg;
}

// ---------------- selective scan ----------------
__global__ void scan_kernel(const float* __restrict__ A_log, const float* __restrict__ Dvec) {
    int g = blockIdx.x * (blockDim.x >> 5) + (threadIdx.x >> 5);
    int lane = threadIdx.x & 31;
    int b  = g / (DI / 2);
    int dp = g % (DI / 2);
    int half = lane >> 4;
    int n = lane & 15;
    int d = dp * 2 + half;

    float Acoef = -expf(A_log[d * DS + n]);
    float Dv = Dvec[d];

    const float* dptr = g_delta + (long)d * BLTOK + b * L_SEQ;
    const float* uptr = g_xconv + (long)d * BLTOK + b * L_SEQ;
    const float* zptr = g_xz + (long)(DI + d) * BLTOK + b * L_SEQ;
    const float* bptr = g_BcT + (long)(b * L_SEQ) * DS + n;
    const float* cptr = g_CcT + (long)(b * L_SEQ) * DS + n;
    float* yptr = g_y + (long)d * BLTOK + b * L_SEQ;

    float s = 0.f;
#pragma unroll 4
    for (int l = 0; l < L_SEQ; l++) {
        float de = dptr[l];
        float u  = uptr[l];
        float zv = zptr[l];
        float Bn = bptr[(long)l * DS];
        float Cn = cptr[(long)l * DS];
        float dA = __expf(de * Acoef);
        s = fmaf(dA, s, de * u * Bn);
        float p = s * Cn;
        p += __shfl_xor_sync(0xffffffffu, p, 8, 16);
        p += __shfl_xor_sync(0xffffffffu, p, 4, 16);
        p += __shfl_xor_sync(0xffffffffu, p, 2, 16);
        p += __shfl_xor_sync(0xffffffffu, p, 1, 16);
        float yv = fmaf(Dv, u, p);
        float sg = 1.f / (1.f + __expf(-zv));
        yv *= zv * sg;
        if (n == 0) yptr[l] = yv;
    }
}

// ---------------- host launcher ----------------
extern "C" void kernel_launch(void* const* d_in, const int* in_sizes, int n_in,
                              void* d_out, int out_size) {
    const float* x     = (const float*)d_in[0];
    const float* embW  = (const float*)d_in[1];
    const float* embB  = (const float*)d_in[2];
    const float* normw = (const float*)d_in[3];
    const float* normb = (const float*)d_in[4];
    const float* inW   = (const float*)d_in[5];
    const float* convw = (const float*)d_in[6];
    const float* convb = (const float*)d_in[7];
    const float* xpW   = (const float*)d_in[8];
    const float* dtW   = (const float*)d_in[9];
    const float* dtb   = (const float*)d_in[10];
    const float* Alog  = (const float*)d_in[11];
    const float* Dv    = (const float*)d_in[12];
    const float* outW  = (const float*)d_in[13];
    const float* nfw   = (const float*)d_in[14];
    const float* nfb   = (const float*)d_in[15];
    float* out = (float*)d_out;

    float *h, *res, *xz, *xconv, *dt, *BcT, *CcT, *delta, *y;
    __nv_bfloat16 *winh, *winl, *wouth, *woutl, *hnh, *hnl, *yh, *yl;
    cudaGetSymbolAddress((void**)&h,     g_h);
    cudaGetSymbolAddress((void**)&res,   g_res);
    cudaGetSymbolAddress((void**)&xz,    g_xz);
    cudaGetSymbolAddress((void**)&xconv, g_xconv);
    cudaGetSymbolAddress((void**)&dt,    g_dt);
    cudaGetSymbolAddress((void**)&BcT,   g_BcT);
    cudaGetSymbolAddress((void**)&CcT,   g_CcT);
    cudaGetSymbolAddress((void**)&delta, g_delta);
    cudaGetSymbolAddress((void**)&y,     g_y);
    cudaGetSymbolAddress((void**)&winh,  g_WinHi);
    cudaGetSymbolAddress((void**)&winl,  g_WinLo);
    cudaGetSymbolAddress((void**)&wouth, g_WoutHi);
    cudaGetSymbolAddress((void**)&woutl, g_WoutLo);
    cudaGetSymbolAddress((void**)&hnh,   g_hnHi);
    cudaGetSymbolAddress((void**)&hnl,   g_hnLo);
    cudaGetSymbolAddress((void**)&yh,    g_yHi);
    cudaGetSymbolAddress((void**)&yl,    g_yLo);

    cudaFuncSetAttribute(mma_gemm_a, cudaFuncAttributeMaxDynamicSharedMemorySize, MMASMEM);
    cudaFuncSetAttribute(mma_gemm_b, cudaFuncAttributeMaxDynamicSharedMemorySize, MMASMEM);

    embed_kernel<<<BLTOK, 256>>>(x, embW, embB);

    for (int lyr = 0; lyr < NLAYER; lyr++) {
        // residual + LN -> hn (bf16 hi/lo, token-major)
        resln_kernel<<<BLTOK, 256>>>(h, res, nullptr, hnh, hnl,
                                     normw + lyr * DM, normb + lyr * DM, lyr > 0 ? 1 : 0);
        // weight conversions
        cvt_pair_kernel<<<(2 * DI * DM + 255) / 256, 256>>>(inW + (long)lyr * 2 * DI * DM, winh, winl, 2 * DI * DM);
        cvt_pair_kernel<<<(DM * DI + 255) / 256, 256>>>(outW + (long)lyr * DM * DI, wouth, woutl, DM * DI);
        // in_proj (tensor cores): xz = Win * hn^T, output (channel, token)
        mma_gemm_a<<<dim3(64, 24), 256, MMASMEM>>>(winh, winl, hnh, hnl, xz, DM, BLTOK);
        // conv + silu
        conv_silu_kernel<<<(DI * BLTOK + 255) / 256, 256>>>(convw + lyr * DI * 4, convb + lyr * DI);
        // x_proj (SIMT)
        sgemm_xproj<<<dim3(64, 3), 256>>>(
            xpW + (long)lyr * (DTR + 2 * DS) * DI, xconv, dt, DTR + 2 * DS, BLTOK, DI, BcT, CcT);
        // dt_proj + softplus (SIMT)
        sgemm_dtproj<<<dim3(64, 12), 256>>>(
            dtW + (long)lyr * DI * DTR, dt, delta, DI, BLTOK, DTR, dtb + lyr * DI);
        // scan
        scan_kernel<<<384, 128>>>(Alog + (long)lyr * DI * DS, Dv + lyr * DI);
        // y -> token-major bf16 hi/lo
        tcvt_kernel<<<dim3(BLTOK / 32, DI / 32), 256>>>(y, yh, yl);
        // out_proj (tensor cores): h[token][e] = Wout * y^T
        mma_gemm_b<<<dim3(64, 6), 256, MMASMEM>>>(wouth, woutl, yh, yl, h, DI, DM);
    }

    resln_kernel<<<BLTOK, 256>>>(h, res, out, nullptr, nullptr, nfw, nfb, 1);
}

// round 8
// speedup vs baseline: 1.0040x; 1.0040x over previous
#include <cuda_runtime.h>
#include <cuda_bf16.h>
#include <math.h>
#include <stdint.h>

#define L_SEQ  4096
#define NB     2
#define BLTOK  8192
#define DM     768
#define DI     1536
#define DS     16
#define DTR    48
#define NLAYER 4

#define NIN_W  (2 * DI * DM)        // per-layer in_proj weight elems
#define NOUT_W (DM * DI)            // per-layer out_proj weight elems

// ---------------- scratch (static device globals) ----------------
__device__ float g_h    [BLTOK * DM];
__device__ float g_res  [BLTOK * DM];
__device__ float g_xz   [2 * DI * BLTOK];   // rows [0,DI): x ; [DI,2DI): z  (channel, token)
__device__ float g_xconv[DI * BLTOK];
__device__ float g_dt   [DTR * BLTOK];
__device__ float g_BcT  [BLTOK * DS];
__device__ float g_CcT  [BLTOK * DS];
__device__ float g_delta[DI * BLTOK];
__device__ float g_y    [DI * BLTOK];       // (channel, token)

__device__ __nv_bfloat16 g_WinHi[NLAYER * NIN_W],  g_WinLo[NLAYER * NIN_W];
__device__ __nv_bfloat16 g_WoutHi[NLAYER * NOUT_W], g_WoutLo[NLAYER * NOUT_W];
__device__ __nv_bfloat16 g_hnHi[BLTOK * DM],  g_hnLo[BLTOK * DM];   // token-major
__device__ __nv_bfloat16 g_yHi[BLTOK * DI],   g_yLo[BLTOK * DI];    // token-major

// ---------------- helpers ----------------
__device__ __forceinline__ uint32_t smem_u32(const void* p) {
    uint32_t a;
    asm("{ .reg .u64 t; cvta.to.shared.u64 t, %1; cvt.u32.u64 %0, t; }" : "=r"(a) : "l"(p));
    return a;
}
#define LDSM_X4(r0, r1, r2, r3, a) \
    asm volatile("ldmatrix.sync.aligned.m8n8.x4.shared.b16 {%0,%1,%2,%3}, [%4];" \
                 : "=r"(r0), "=r"(r1), "=r"(r2), "=r"(r3) : "r"(a))
#define MMA_BF16(c, a0, a1, a2, a3, b0, b1) \
    asm volatile("mma.sync.aligned.m16n8k16.row.col.f32.bf16.bf16.f32 " \
                 "{%0,%1,%2,%3}, {%4,%5,%6,%7}, {%8,%9}, {%0,%1,%2,%3};" \
                 : "+f"((c)[0]), "+f"((c)[1]), "+f"((c)[2]), "+f"((c)[3]) \
                 : "r"(a0), "r"(a1), "r"(a2), "r"(a3), "r"(b0), "r"(b1))
#define CP_A16(dst, src) \
    asm volatile("cp.async.cg.shared.global [%0], [%1], 16;" :: "r"(dst), "l"(src))
#define CP_COMMIT()  asm volatile("cp.async.commit_group;")
#define CP_WAIT(n)   asm volatile("cp.async.wait_group %0;" :: "n"(n))

// ---------------- mma.sync 3xBF16 GEMM: C = A(MxK) * B(NtokxK)^T ----------------
// LAYOUT 0: C[(bm+m)*ldc + bn+n]   LAYOUT 1: C[(bn+n)*ldc + bm+m]
#define TILE_B  10240              // 128*80
#define STAGE_B 40960              // 4 tiles
#define EPI_STRIDE 130             // floats
#define MMASMEM 81920              // 2 stages (>= epi staging 66560)

template <int LAYOUT>
__device__ __forceinline__ void mma_gemm_body(
    char* dsm,
    const __nv_bfloat16* __restrict__ Ahi, const __nv_bfloat16* __restrict__ Alo,
    const __nv_bfloat16* __restrict__ Bhi, const __nv_bfloat16* __restrict__ Blo,
    float* __restrict__ C, int K, int ldc) {
    const int tid = threadIdx.x;
    const int wid = tid >> 5;
    const int lane = tid & 31;
    const int bm = blockIdx.y * 128;
    const int bn = blockIdx.x * 128;
    const int wm = (wid >> 2) * 64;
    const int wn = (wid & 3) * 32;

    const uint32_t sb = smem_u32(dsm);

    uint32_t so[2];
    size_t offA[2], offB[2];
#pragma unroll
    for (int j = 0; j < 2; j++) {
        int v = tid + j * 256;
        int row = v >> 2, c = v & 3;
        so[j] = row * 80 + c * 16;
        offA[j] = (size_t)(bm + row) * K + c * 8;
        offB[j] = (size_t)(bn + row) * K + c * 8;
    }

    uint32_t aoff[4], boff[2];
    {
        int g = lane >> 3, r = lane & 7;
#pragma unroll
        for (int mt = 0; mt < 4; mt++) {
            int row = wm + mt * 16 + (g & 1) * 8 + r;
            aoff[mt] = row * 80 + (g >> 1) * 16;
        }
#pragma unroll
        for (int p = 0; p < 2; p++) {
            int row = wn + p * 16 + (g >> 1) * 8 + r;
            boff[p] = row * 80 + (g & 1) * 16;
        }
    }

    const int KT = K >> 5;   // BK = 32

    auto issue = [&](int kc, int stg) {
        int k0 = kc << 5;
        uint32_t base = sb + stg * STAGE_B;
#pragma unroll
        for (int j = 0; j < 2; j++) {
            uint32_t d = base + so[j];
            CP_A16(d,              Ahi + offA[j] + k0);
            CP_A16(d + TILE_B,     Alo + offA[j] + k0);
            CP_A16(d + 2 * TILE_B, Bhi + offB[j] + k0);
            CP_A16(d + 3 * TILE_B, Blo + offB[j] + k0);
        }
        CP_COMMIT();
    };

    float acc[4][4][4];
#pragma unroll
    for (int mt = 0; mt < 4; mt++)
#pragma unroll
        for (int nt = 0; nt < 4; nt++)
#pragma unroll
            for (int e = 0; e < 4; e++) acc[mt][nt][e] = 0.f;

    issue(0, 0);
    if (KT > 1) issue(1, 1);

    for (int kc = 0; kc < KT; kc++) {
        if (kc + 1 < KT) CP_WAIT(1); else CP_WAIT(0);
        __syncthreads();
        uint32_t base = sb + (kc & 1) * STAGE_B;
        uint32_t sAh = base, sAl = base + TILE_B, sBh = base + 2 * TILE_B, sBl = base + 3 * TILE_B;
#pragma unroll
        for (int ks = 0; ks < 2; ks++) {
            uint32_t kb = ks * 32;
            uint32_t bh[2][4], bl[2][4];
#pragma unroll
            for (int p = 0; p < 2; p++) {
                LDSM_X4(bh[p][0], bh[p][1], bh[p][2], bh[p][3], sBh + boff[p] + kb);
                LDSM_X4(bl[p][0], bl[p][1], bl[p][2], bl[p][3], sBl + boff[p] + kb);
            }
#pragma unroll
            for (int mt = 0; mt < 4; mt++) {
                uint32_t ah[4], al[4];
                LDSM_X4(ah[0], ah[1], ah[2], ah[3], sAh + aoff[mt] + kb);
                LDSM_X4(al[0], al[1], al[2], al[3], sAl + aoff[mt] + kb);
#pragma unroll
                for (int nt = 0; nt < 4; nt++) {
                    int p = nt >> 1, h = (nt & 1) * 2;
                    MMA_BF16(acc[mt][nt], ah[0], ah[1], ah[2], ah[3], bh[p][h], bh[p][h + 1]);
                    MMA_BF16(acc[mt][nt], ah[0], ah[1], ah[2], ah[3], bl[p][h], bl[p][h + 1]);
                    MMA_BF16(acc[mt][nt], al[0], al[1], al[2], al[3], bh[p][h], bh[p][h + 1]);
                }
            }
        }
        __syncthreads();
        if (kc + 2 < KT) issue(kc + 2, kc & 1);
    }

    float* st = (float*)dsm;
    {
        int mr = lane >> 2;
        int nc = (lane & 3) * 2;
#pragma unroll
        for (int mt = 0; mt < 4; mt++) {
#pragma unroll
            for (int nt = 0; nt < 4; nt++) {
                int m0 = wm + mt * 16 + mr;
                int n0 = wn + nt * 8 + nc;
                *(float2*)(st + m0 * EPI_STRIDE + n0) = make_float2(acc[mt][nt][0], acc[mt][nt][1]);
                *(float2*)(st + (m0 + 8) * EPI_STRIDE + n0) = make_float2(acc[mt][nt][2], acc[mt][nt][3]);
            }
        }
    }
    __syncthreads();
    if (LAYOUT == 0) {
        for (int idx = tid; idx < 16384; idx += 256) {
            int r = idx >> 7, c = idx & 127;
            C[(size_t)(bm + r) * ldc + bn + c] = st[r * EPI_STRIDE + c];
        }
    } else {
        for (int idx = tid; idx < 16384; idx += 256) {
            int n = idx >> 7, m = idx & 127;
            C[(size_t)(bn + n) * ldc + bm + m] = st[m * EPI_STRIDE + n];
        }
    }
}

__global__ void __launch_bounds__(256, 2) mma_gemm_a(
    const __nv_bfloat16* __restrict__ Ahi, const __nv_bfloat16* __restrict__ Alo,
    const __nv_bfloat16* __restrict__ Bhi, const __nv_bfloat16* __restrict__ Blo,
    float* __restrict__ C, int K, int ldc) {
    extern __shared__ char dsm[];
    mma_gemm_body<0>(dsm, Ahi, Alo, Bhi, Blo, C, K, ldc);
}
__global__ void __launch_bounds__(256, 2) mma_gemm_b(
    const __nv_bfloat16* __restrict__ Ahi, const __nv_bfloat16* __restrict__ Alo,
    const __nv_bfloat16* __restrict__ Bhi, const __nv_bfloat16* __restrict__ Blo,
    float* __restrict__ C, int K, int ldc) {
    extern __shared__ char dsm[];
    mma_gemm_body<1>(dsm, Ahi, Alo, Bhi, Blo, C, K, ldc);
}

// ---------------- all-layer weight fp32 -> bf16 hi/lo (one launch) ----------------
#define CVT_TOTAL (NLAYER * (NIN_W + NOUT_W))
__global__ void cvt_all_kernel(const float* __restrict__ inW, const float* __restrict__ outW) {
    int i = blockIdx.x * 256 + threadIdx.x;
    if (i >= CVT_TOTAL) return;
    float v;
    __nv_bfloat16 *hi, *lo;
    if (i < NLAYER * NIN_W) {
        v = inW[i];
        hi = g_WinHi + i; lo = g_WinLo + i;
    } else {
        int j = i - NLAYER * NIN_W;
        v = outW[j];
        hi = g_WoutHi + j; lo = g_WoutLo + j;
    }
    __nv_bfloat16 h = __float2bfloat16(v);
    *hi = h;
    *lo = __float2bfloat16(v - __bfloat162float(h));
}

// ---------------- transpose (d,tok)->(tok,d) + bf16 hi/lo ----------------
__global__ void tcvt_kernel(const float* __restrict__ src, __nv_bfloat16* __restrict__ hi,
                            __nv_bfloat16* __restrict__ lo) {
    __shared__ float t[32][33];
    int tx = threadIdx.x & 31, ty = threadIdx.x >> 5;
    int tok0 = blockIdx.x * 32, d0 = blockIdx.y * 32;
#pragma unroll
    for (int i = 0; i < 4; i++) {
        int d = d0 + ty + i * 8;
        t[ty + i * 8][tx] = src[(size_t)d * BLTOK + tok0 + tx];
    }
    __syncthreads();
#pragma unroll
    for (int i = 0; i < 4; i++) {
        int tok = tok0 + ty + i * 8;
        float v = t[tx][ty + i * 8];
        __nv_bfloat16 h = __float2bfloat16(v);
        size_t o = (size_t)tok * DI + d0 + tx;
        hi[o] = h;
        lo[o] = __float2bfloat16(v - __bfloat162float(h));
    }
}

// ---------------- embed ----------------
__global__ void embed_kernel(const float* __restrict__ x, const float* __restrict__ W,
                             const float* __restrict__ bias) {
    __shared__ float xs[64];
    int tok = blockIdx.x;
    int b = tok >> 12, l = tok & 4095;
    int tid = threadIdx.x;
    if (tid < 64) xs[tid] = x[(b * 64 + tid) * L_SEQ + l];
    __syncthreads();
    for (int e = tid; e < DM; e += 256) {
        const float* w = W + e * 64;
        float acc = bias[e];
#pragma unroll 16
        for (int i = 0; i < 64; i++) acc = fmaf(w[i], xs[i], acc);
        g_h[tok * DM + e] = acc;
    }
}

// ---------------- fused residual + layernorm (+ bf16 hi/lo out) ----------------
__global__ void resln_kernel(const float* __restrict__ src, float* __restrict__ res,
                             float* __restrict__ outf, __nv_bfloat16* __restrict__ ohi,
                             __nv_bfloat16* __restrict__ olo,
                             const float* __restrict__ w, const float* __restrict__ b, int add) {
    __shared__ float red1[8], red2[8];
    int base = blockIdx.x * DM;
    int tid = threadIdx.x;
    float v0 = src[base + tid];
    float v1 = src[base + tid + 256];
    float v2 = src[base + tid + 512];
    if (add) {
        v0 += res[base + tid];
        v1 += res[base + tid + 256];
        v2 += res[base + tid + 512];
    }
    res[base + tid]       = v0;
    res[base + tid + 256] = v1;
    res[base + tid + 512] = v2;

    float s = v0 + v1 + v2;
#pragma unroll
    for (int o = 16; o; o >>= 1) s += __shfl_xor_sync(0xffffffffu, s, o);
    if ((tid & 31) == 0) red1[tid >> 5] = s;
    __syncthreads();
    float tot = 0.f;
#pragma unroll
    for (int i = 0; i < 8; i++) tot += red1[i];
    float mean = tot * (1.f / DM);

    float d0 = v0 - mean, d1 = v1 - mean, d2 = v2 - mean;
    float sq = d0 * d0 + d1 * d1 + d2 * d2;
#pragma unroll
    for (int o = 16; o; o >>= 1) sq += __shfl_xor_sync(0xffffffffu, sq, o);
    if ((tid & 31) == 0) red2[tid >> 5] = sq;
    __syncthreads();
    float vt = 0.f;
#pragma unroll
    for (int i = 0; i < 8; i++) vt += red2[i];
    float inv = rsqrtf(vt * (1.f / DM) + 1e-5f);

    float o0 = d0 * inv * w[tid]       + b[tid];
    float o1 = d1 * inv * w[tid + 256] + b[tid + 256];
    float o2 = d2 * inv * w[tid + 512] + b[tid + 512];
    if (outf) {
        outf[base + tid]       = o0;
        outf[base + tid + 256] = o1;
        outf[base + tid + 512] = o2;
    } else {
        __nv_bfloat16 h0 = __float2bfloat16(o0), h1 = __float2bfloat16(o1), h2 = __float2bfloat16(o2);
        ohi[base + tid]       = h0;  olo[base + tid]       = __float2bfloat16(o0 - __bfloat162float(h0));
        ohi[base + tid + 256] = h1;  olo[base + tid + 256] = __float2bfloat16(o1 - __bfloat162float(h1));
        ohi[base + tid + 512] = h2;  olo[base + tid + 512] = __float2bfloat16(o2 - __bfloat162float(h2));
    }
}

// ---------------- SIMT SGEMM (x_proj / dt_proj) ----------------
#define BK 16
#define SPAD 4
enum { EPI_STORE = 0, EPI_SOFTPLUS = 1, EPI_TRANS = 2, EPI_XPROJ = 3 };

template <int BM, int BN, int TM, int TN, bool BNT, int EPI>
__device__ __forceinline__ void sgemm_body(
    const float* __restrict__ A, const float* __restrict__ B, float* __restrict__ C,
    int M, int N, int K, const float* __restrict__ bias,
    float* __restrict__ aux1, float* __restrict__ aux2) {
    constexpr int AE = BM * BK / 256;
    constexpr int BE = BN * BK / 256;
    __shared__ float As[BK][BM + SPAD];
    __shared__ float Bs[BK][BN + SPAD];

    int tid = threadIdx.x;
    int bm = blockIdx.y * BM;
    int bn = blockIdx.x * BN;
    int tx = tid % (BN / TN);
    int ty = tid / (BN / TN);

    float acc[TM][TN];
#pragma unroll
    for (int i = 0; i < TM; i++)
#pragma unroll
        for (int j = 0; j < TN; j++) acc[i][j] = 0.f;

    float pa[AE], pb[BE];
    auto loadA = [&](int k0) {
#pragma unroll
        for (int e = 0; e < AE; e++) {
            int i = tid + e * 256;
            int r = i / BK, kk = i % BK;
            int m = bm + r;
            pa[e] = (m < M) ? A[(long)m * K + k0 + kk] : 0.f;
        }
    };
    auto loadB = [&](int k0) {
#pragma unroll
        for (int e = 0; e < BE; e++) {
            int i = tid + e * 256;
            if (BNT) {
                int r = i / BK, kk = i % BK;
                pb[e] = B[(long)(bn + r) * K + k0 + kk];
            } else {
                int kk = i / BN, c = i % BN;
                pb[e] = B[(long)(k0 + kk) * N + bn + c];
            }
        }
    };
    auto storeAB = [&]() {
#pragma unroll
        for (int e = 0; e < AE; e++) {
            int i = tid + e * 256;
            As[i % BK][i / BK] = pa[e];
        }
#pragma unroll
        for (int e = 0; e < BE; e++) {
            int i = tid + e * 256;
            if (BNT) Bs[i % BK][i / BK] = pb[e];
            else     Bs[i / BN][i % BN] = pb[e];
        }
    };

    int KT = K / BK;
    loadA(0); loadB(0);
    storeAB();
    __syncthreads();

    for (int kt = 0; kt < KT; kt++) {
        if (kt + 1 < KT) { loadA((kt + 1) * BK); loadB((kt + 1) * BK); }
#pragma unroll
        for (int kk = 0; kk < BK; kk++) {
            float a[TM], bf[TN];
#pragma unroll
            for (int i = 0; i < TM; i++) a[i] = As[kk][ty * TM + i];
#pragma unroll
            for (int j = 0; j < TN; j++) bf[j] = Bs[kk][tx * TN + j];
#pragma unroll
            for (int i = 0; i < TM; i++)
#pragma unroll
                for (int j = 0; j < TN; j++) acc[i][j] = fmaf(a[i], bf[j], acc[i][j]);
        }
        __syncthreads();
        if (kt + 1 < KT) {
            storeAB();
            __syncthreads();
        }
    }

#pragma unroll
    for (int i = 0; i < TM; i++) {
        int m = bm + ty * TM + i;
        if (m >= M) continue;
#pragma unroll
        for (int j = 0; j < TN; j++) {
            int n = bn + tx * TN + j;
            float v = acc[i][j];
            if (EPI == EPI_STORE) {
                C[(long)m * N + n] = v;
            } else if (EPI == EPI_SOFTPLUS) {
                v += bias[m];
                C[(long)m * N + n] = (v > 20.f) ? v : log1pf(expf(v));
            } else if (EPI == EPI_TRANS) {
                C[(long)n * M + m] = v;
            } else {
                if (m < DTR)            C[(long)m * N + n] = v;
                else if (m < DTR + DS)  aux1[(long)n * DS + (m - DTR)] = v;
                else                    aux2[(long)n * DS + (m - DTR - DS)] = v;
            }
        }
    }
}

__global__ void __launch_bounds__(256, 2) sgemm_xproj(
    const float* __restrict__ A, const float* __restrict__ B, float* __restrict__ C,
    int M, int N, int K, float* __restrict__ aux1, float* __restrict__ aux2) {
    sgemm_body<32, 128, 2, 8, false, EPI_XPROJ>(A, B, C, M, N, K, nullptr, aux1, aux2);
}
__global__ void __launch_bounds__(256, 2) sgemm_dtproj(
    const float* __restrict__ A, const float* __restrict__ B, float* __restrict__ C,
    int M, int N, int K, const float* __restrict__ bias) {
    sgemm_body<128, 128, 8, 8, false, EPI_SOFTPLUS>(A, B, C, M, N, K, bias, nullptr, nullptr);
}

// ---------------- depthwise causal conv1d + bias + SiLU ----------------
__global__ void conv_silu_kernel(const float* __restrict__ cw, const float* __restrict__ cb) {
    int idx = blockIdx.x * 256 + threadIdx.x;
    if (idx >= DI * BLTOK) return;
    int d = idx >> 13;
    int bl = idx & 8191;
    int l = bl & 4095;
    const float* xp = g_xz + (long)d * BLTOK + bl;
    float w0 = cw[d * 4], w1 = cw[d * 4 + 1], w2 = cw[d * 4 + 2], w3 = cw[d * 4 + 3];
    float acc = cb[d];
    if (l >= 3) acc = fmaf(w0, xp[-3], acc);
    if (l >= 2) acc = fmaf(w1, xp[-2], acc);
    if (l >= 1) acc = fmaf(w2, xp[-1], acc);
    acc = fmaf(w3, xp[0], acc);
    float sg = 1.f / (1.f + __expf(-acc));
    g_xconv[idx] = acc * sg;
}

// ---------------- selective scan ----------------
__global__ void scan_kernel(const float* __restrict__ A_log, const float* __restrict__ Dvec) {
    int g = blockIdx.x * (blockDim.x >> 5) + (threadIdx.x >> 5);
    int lane = threadIdx.x & 31;
    int b  = g / (DI / 2);
    int dp = g % (DI / 2);
    int half = lane >> 4;
    int n = lane & 15;
    int d = dp * 2 + half;

    float Acoef = -expf(A_log[d * DS + n]);
    float Dv = Dvec[d];

    const float* dptr = g_delta + (long)d * BLTOK + b * L_SEQ;
    const float* uptr = g_xconv + (long)d * BLTOK + b * L_SEQ;
    const float* zptr = g_xz + (long)(DI + d) * BLTOK + b * L_SEQ;
    const float* bptr = g_BcT + (long)(b * L_SEQ) * DS + n;
    const float* cptr = g_CcT + (long)(b * L_SEQ) * DS + n;
    float* yptr = g_y + (long)d * BLTOK + b * L_SEQ;

    float s = 0.f;
#pragma unroll 4
    for (int l = 0; l < L_SEQ; l++) {
        float de = dptr[l];
        float u  = uptr[l];
        float zv = zptr[l];
        float Bn = bptr[(long)l * DS];
        float Cn = cptr[(long)l * DS];
        float dA = __expf(de * Acoef);
        s = fmaf(dA, s, de * u * Bn);
        float p = s * Cn;
        p += __shfl_xor_sync(0xffffffffu, p, 8, 16);
        p += __shfl_xor_sync(0xffffffffu, p, 4, 16);
        p += __shfl_xor_sync(0xffffffffu, p, 2, 16);
        p += __shfl_xor_sync(0xffffffffu, p, 1, 16);
        float yv = fmaf(Dv, u, p);
        float sg = 1.f / (1.f + __expf(-zv));
        yv *= zv * sg;
        if (n == 0) yptr[l] = yv;
    }
}

// ---------------- host launcher ----------------
extern "C" void kernel_launch(void* const* d_in, const int* in_sizes, int n_in,
                              void* d_out, int out_size) {
    const float* x     = (const float*)d_in[0];
    const float* embW  = (const float*)d_in[1];
    const float* embB  = (const float*)d_in[2];
    const float* normw = (const float*)d_in[3];
    const float* normb = (const float*)d_in[4];
    const float* inW   = (const float*)d_in[5];
    const float* convw = (const float*)d_in[6];
    const float* convb = (const float*)d_in[7];
    const float* xpW   = (const float*)d_in[8];
    const float* dtW   = (const float*)d_in[9];
    const float* dtb   = (const float*)d_in[10];
    const float* Alog  = (const float*)d_in[11];
    const float* Dv    = (const float*)d_in[12];
    const float* outW  = (const float*)d_in[13];
    const float* nfw   = (const float*)d_in[14];
    const float* nfb   = (const float*)d_in[15];
    float* out = (float*)d_out;

    float *h, *res, *xz, *xconv, *dt, *BcT, *CcT, *delta, *y;
    __nv_bfloat16 *winh, *winl, *wouth, *woutl, *hnh, *hnl, *yh, *yl;
    cudaGetSymbolAddress((void**)&h,     g_h);
    cudaGetSymbolAddress((void**)&res,   g_res);
    cudaGetSymbolAddress((void**)&xz,    g_xz);
    cudaGetSymbolAddress((void**)&xconv, g_xconv);
    cudaGetSymbolAddress((void**)&dt,    g_dt);
    cudaGetSymbolAddress((void**)&BcT,   g_BcT);
    cudaGetSymbolAddress((void**)&CcT,   g_CcT);
    cudaGetSymbolAddress((void**)&delta, g_delta);
    cudaGetSymbolAddress((void**)&y,     g_y);
    cudaGetSymbolAddress((void**)&winh,  g_WinHi);
    cudaGetSymbolAddress((void**)&winl,  g_WinLo);
    cudaGetSymbolAddress((void**)&wouth, g_WoutHi);
    cudaGetSymbolAddress((void**)&woutl, g_WoutLo);
    cudaGetSymbolAddress((void**)&hnh,   g_hnHi);
    cudaGetSymbolAddress((void**)&hnl,   g_hnLo);
    cudaGetSymbolAddress((void**)&yh,    g_yHi);
    cudaGetSymbolAddress((void**)&yl,    g_yLo);

    cudaFuncSetAttribute(mma_gemm_a, cudaFuncAttributeMaxDynamicSharedMemorySize, MMASMEM);
    cudaFuncSetAttribute(mma_gemm_b, cudaFuncAttributeMaxDynamicSharedMemorySize, MMASMEM);

    // launch order chosen so mma_gemm_a is launch index 3 (ncu capture point)
    embed_kernel<<<BLTOK, 256>>>(x, embW, embB);                                   // 0
    cvt_all_kernel<<<(CVT_TOTAL + 255) / 256, 256>>>(inW, outW);                   // 1

    for (int lyr = 0; lyr < NLAYER; lyr++) {
        resln_kernel<<<BLTOK, 256>>>(h, res, nullptr, hnh, hnl,                    // 2
                                     normw + lyr * DM, normb + lyr * DM, lyr > 0 ? 1 : 0);
        mma_gemm_a<<<dim3(64, 24), 256, MMASMEM>>>(                                // 3 <- profiled
            winh + (size_t)lyr * NIN_W, winl + (size_t)lyr * NIN_W, hnh, hnl, xz, DM, BLTOK);
        conv_silu_kernel<<<(DI * BLTOK + 255) / 256, 256>>>(convw + lyr * DI * 4, convb + lyr * DI);
        sgemm_xproj<<<dim3(64, 3), 256>>>(
            xpW + (long)lyr * (DTR + 2 * DS) * DI, xconv, dt, DTR + 2 * DS, BLTOK, DI, BcT, CcT);
        sgemm_dtproj<<<dim3(64, 12), 256>>>(
            dtW + (long)lyr * DI * DTR, dt, delta, DI, BLTOK, DTR, dtb + lyr * DI);
        scan_kernel<<<384, 128>>>(Alog + (long)lyr * DI * DS, Dv + lyr * DI);
        tcvt_kernel<<<dim3(BLTOK / 32, DI / 32), 256>>>(y, yh, yl);
        mma_gemm_b<<<dim3(64, 6), 256, MMASMEM>>>(
            wouth + (size_t)lyr * NOUT_W, woutl + (size_t)lyr * NOUT_W, yh, yl, h, DI, DM);
    }

    resln_kernel<<<BLTOK, 256>>>(h, res, out, nullptr, nullptr, nfw, nfb, 1);
}

// round 10
// speedup vs baseline: 1.5952x; 1.5889x over previous
#include <cuda_runtime.h>
#include <cuda_bf16.h>
#include <math.h>
#include <stdint.h>

#define L_SEQ  4096
#define NB     2
#define BLTOK  8192
#define DM     768
#define DI     1536
#define DS     16
#define DTR    48
#define NLAYER 4

#define NIN_W  (2 * DI * DM)
#define NOUT_W (DM * DI)

#define SCH 64   // scan chunks
#define SCL 64   // chunk length (SCH*SCL = L_SEQ)

// ---------------- scratch (static device globals) ----------------
__device__ float g_h    [BLTOK * DM];
__device__ float g_res  [BLTOK * DM];
__device__ float g_xz   [2 * DI * BLTOK];   // rows [0,DI): x ; [DI,2DI): z  (channel, token)
__device__ float g_xconv[DI * BLTOK];
__device__ float g_dt   [DTR * BLTOK];
__device__ float g_BcT  [BLTOK * DS];
__device__ float g_CcT  [BLTOK * DS];
__device__ float g_delta[DI * BLTOK];
__device__ float g_y    [DI * BLTOK];       // (channel, token)

__device__ float g_P [NB * SCH * DI * DS];  // chunk products   (b, c, d, n)
__device__ float g_Q [NB * SCH * DI * DS];  // chunk local scans
__device__ float g_S0[NB * SCH * DI * DS];  // chunk initial states

__device__ __nv_bfloat16 g_WinHi[NLAYER * NIN_W],  g_WinLo[NLAYER * NIN_W];
__device__ __nv_bfloat16 g_WoutHi[NLAYER * NOUT_W], g_WoutLo[NLAYER * NOUT_W];
__device__ __nv_bfloat16 g_hnHi[BLTOK * DM],  g_hnLo[BLTOK * DM];   // token-major
__device__ __nv_bfloat16 g_yHi[BLTOK * DI],   g_yLo[BLTOK * DI];    // token-major

// ---------------- helpers ----------------
__device__ __forceinline__ uint32_t smem_u32(const void* p) {
    uint32_t a;
    asm("{ .reg .u64 t; cvta.to.shared.u64 t, %1; cvt.u32.u64 %0, t; }" : "=r"(a) : "l"(p));
    return a;
}
#define LDSM_X4(r0, r1, r2, r3, a) \
    asm volatile("ldmatrix.sync.aligned.m8n8.x4.shared.b16 {%0,%1,%2,%3}, [%4];" \
                 : "=r"(r0), "=r"(r1), "=r"(r2), "=r"(r3) : "r"(a))
#define MMA_BF16(c, a0, a1, a2, a3, b0, b1) \
    asm volatile("mma.sync.aligned.m16n8k16.row.col.f32.bf16.bf16.f32 " \
                 "{%0,%1,%2,%3}, {%4,%5,%6,%7}, {%8,%9}, {%0,%1,%2,%3};" \
                 : "+f"((c)[0]), "+f"((c)[1]), "+f"((c)[2]), "+f"((c)[3]) \
                 : "r"(a0), "r"(a1), "r"(a2), "r"(a3), "r"(b0), "r"(b1))
#define CP_A16(dst, src) \
    asm volatile("cp.async.cg.shared.global [%0], [%1], 16;" :: "r"(dst), "l"(src))
#define CP_COMMIT()  asm volatile("cp.async.commit_group;")
#define CP_WAIT(n)   asm volatile("cp.async.wait_group %0;" :: "n"(n))

// ---------------- mma.sync 3xBF16 GEMM ----------------
#define TILE_B  10240
#define STAGE_B 40960
#define EPI_STRIDE 130
#define MMASMEM 81920

template <int LAYOUT>
__device__ __forceinline__ void mma_gemm_body(
    char* dsm,
    const __nv_bfloat16* __restrict__ Ahi, const __nv_bfloat16* __restrict__ Alo,
    const __nv_bfloat16* __restrict__ Bhi, const __nv_bfloat16* __restrict__ Blo,
    float* __restrict__ C, int K, int ldc) {
    const int tid = threadIdx.x;
    const int wid = tid >> 5;
    const int lane = tid & 31;
    const int bm = blockIdx.y * 128;
    const int bn = blockIdx.x * 128;
    const int wm = (wid >> 2) * 64;
    const int wn = (wid & 3) * 32;

    const uint32_t sb = smem_u32(dsm);

    uint32_t so[2];
    size_t offA[2], offB[2];
#pragma unroll
    for (int j = 0; j < 2; j++) {
        int v = tid + j * 256;
        int row = v >> 2, c = v & 3;
        so[j] = row * 80 + c * 16;
        offA[j] = (size_t)(bm + row) * K + c * 8;
        offB[j] = (size_t)(bn + row) * K + c * 8;
    }

    uint32_t aoff[4], boff[2];
    {
        int g = lane >> 3, r = lane & 7;
#pragma unroll
        for (int mt = 0; mt < 4; mt++) {
            int row = wm + mt * 16 + (g & 1) * 8 + r;
            aoff[mt] = row * 80 + (g >> 1) * 16;
        }
#pragma unroll
        for (int p = 0; p < 2; p++) {
            int row = wn + p * 16 + (g >> 1) * 8 + r;
            boff[p] = row * 80 + (g & 1) * 16;
        }
    }

    const int KT = K >> 5;

    auto issue = [&](int kc, int stg) {
        int k0 = kc << 5;
        uint32_t base = sb + stg * STAGE_B;
#pragma unroll
        for (int j = 0; j < 2; j++) {
            uint32_t d = base + so[j];
            CP_A16(d,              Ahi + offA[j] + k0);
            CP_A16(d + TILE_B,     Alo + offA[j] + k0);
            CP_A16(d + 2 * TILE_B, Bhi + offB[j] + k0);
            CP_A16(d + 3 * TILE_B, Blo + offB[j] + k0);
        }
        CP_COMMIT();
    };

    float acc[4][4][4];
#pragma unroll
    for (int mt = 0; mt < 4; mt++)
#pragma unroll
        for (int nt = 0; nt < 4; nt++)
#pragma unroll
            for (int e = 0; e < 4; e++) acc[mt][nt][e] = 0.f;

    issue(0, 0);
    if (KT > 1) issue(1, 1);

    for (int kc = 0; kc < KT; kc++) {
        if (kc + 1 < KT) CP_WAIT(1); else CP_WAIT(0);
        __syncthreads();
        uint32_t base = sb + (kc & 1) * STAGE_B;
        uint32_t sAh = base, sAl = base + TILE_B, sBh = base + 2 * TILE_B, sBl = base + 3 * TILE_B;
#pragma unroll
        for (int ks = 0; ks < 2; ks++) {
            uint32_t kb = ks * 32;
            uint32_t bh[2][4], bl[2][4];
#pragma unroll
            for (int p = 0; p < 2; p++) {
                LDSM_X4(bh[p][0], bh[p][1], bh[p][2], bh[p][3], sBh + boff[p] + kb);
                LDSM_X4(bl[p][0], bl[p][1], bl[p][2], bl[p][3], sBl + boff[p] + kb);
            }
#pragma unroll
            for (int mt = 0; mt < 4; mt++) {
                uint32_t ah[4], al[4];
                LDSM_X4(ah[0], ah[1], ah[2], ah[3], sAh + aoff[mt] + kb);
                LDSM_X4(al[0], al[1], al[2], al[3], sAl + aoff[mt] + kb);
#pragma unroll
                for (int nt = 0; nt < 4; nt++) {
                    int p = nt >> 1, h = (nt & 1) * 2;
                    MMA_BF16(acc[mt][nt], ah[0], ah[1], ah[2], ah[3], bh[p][h], bh[p][h + 1]);
                    MMA_BF16(acc[mt][nt], ah[0], ah[1], ah[2], ah[3], bl[p][h], bl[p][h + 1]);
                    MMA_BF16(acc[mt][nt], al[0], al[1], al[2], al[3], bh[p][h], bh[p][h + 1]);
                }
            }
        }
        __syncthreads();
        if (kc + 2 < KT) issue(kc + 2, kc & 1);
    }

    float* st = (float*)dsm;
    {
        int mr = lane >> 2;
        int nc = (lane & 3) * 2;
#pragma unroll
        for (int mt = 0; mt < 4; mt++) {
#pragma unroll
            for (int nt = 0; nt < 4; nt++) {
                int m0 = wm + mt * 16 + mr;
                int n0 = wn + nt * 8 + nc;
                *(float2*)(st + m0 * EPI_STRIDE + n0) = make_float2(acc[mt][nt][0], acc[mt][nt][1]);
                *(float2*)(st + (m0 + 8) * EPI_STRIDE + n0) = make_float2(acc[mt][nt][2], acc[mt][nt][3]);
            }
        }
    }
    __syncthreads();
    if (LAYOUT == 0) {
        for (int idx = tid; idx < 16384; idx += 256) {
            int r = idx >> 7, c = idx & 127;
            C[(size_t)(bm + r) * ldc + bn + c] = st[r * EPI_STRIDE + c];
        }
    } else {
        for (int idx = tid; idx < 16384; idx += 256) {
            int n = idx >> 7, m = idx & 127;
            C[(size_t)(bn + n) * ldc + bm + m] = st[m * EPI_STRIDE + n];
        }
    }
}

__global__ void __launch_bounds__(256, 2) mma_gemm_a(
    const __nv_bfloat16* __restrict__ Ahi, const __nv_bfloat16* __restrict__ Alo,
    const __nv_bfloat16* __restrict__ Bhi, const __nv_bfloat16* __restrict__ Blo,
    float* __restrict__ C, int K, int ldc) {
    extern __shared__ char dsm[];
    mma_gemm_body<0>(dsm, Ahi, Alo, Bhi, Blo, C, K, ldc);
}
__global__ void __launch_bounds__(256, 2) mma_gemm_b(
    const __nv_bfloat16* __restrict__ Ahi, const __nv_bfloat16* __restrict__ Alo,
    const __nv_bfloat16* __restrict__ Bhi, const __nv_bfloat16* __restrict__ Blo,
    float* __restrict__ C, int K, int ldc) {
    extern __shared__ char dsm[];
    mma_gemm_body<1>(dsm, Ahi, Alo, Bhi, Blo, C, K, ldc);
}

// ---------------- all-layer weight fp32 -> bf16 hi/lo ----------------
#define CVT_TOTAL (NLAYER * (NIN_W + NOUT_W))
__global__ void cvt_all_kernel(const float* __restrict__ inW, const float* __restrict__ outW) {
    int i = blockIdx.x * 256 + threadIdx.x;
    if (i >= CVT_TOTAL) return;
    float v;
    __nv_bfloat16 *hi, *lo;
    if (i < NLAYER * NIN_W) {
        v = inW[i];
        hi = g_WinHi + i; lo = g_WinLo + i;
    } else {
        int j = i - NLAYER * NIN_W;
        v = outW[j];
        hi = g_WoutHi + j; lo = g_WoutLo + j;
    }
    __nv_bfloat16 h = __float2bfloat16(v);
    *hi = h;
    *lo = __float2bfloat16(v - __bfloat162float(h));
}

// ---------------- transpose (d,tok)->(tok,d) + bf16 hi/lo ----------------
__global__ void tcvt_kernel(const float* __restrict__ src, __nv_bfloat16* __restrict__ hi,
                            __nv_bfloat16* __restrict__ lo) {
    __shared__ float t[32][33];
    int tx = threadIdx.x & 31, ty = threadIdx.x >> 5;
    int tok0 = blockIdx.x * 32, d0 = blockIdx.y * 32;
#pragma unroll
    for (int i = 0; i < 4; i++) {
        int d = d0 + ty + i * 8;
        t[ty + i * 8][tx] = src[(size_t)d * BLTOK + tok0 + tx];
    }
    __syncthreads();
#pragma unroll
    for (int i = 0; i < 4; i++) {
        int tok = tok0 + ty + i * 8;
        float v = t[tx][ty + i * 8];
        __nv_bfloat16 h = __float2bfloat16(v);
        size_t o = (size_t)tok * DI + d0 + tx;
        hi[o] = h;
        lo[o] = __float2bfloat16(v - __bfloat162float(h));
    }
}

// ---------------- embed ----------------
__global__ void embed_kernel(const float* __restrict__ x, const float* __restrict__ W,
                             const float* __restrict__ bias) {
    __shared__ float xs[64];
    int tok = blockIdx.x;
    int b = tok >> 12, l = tok & 4095;
    int tid = threadIdx.x;
    if (tid < 64) xs[tid] = x[(b * 64 + tid) * L_SEQ + l];
    __syncthreads();
    for (int e = tid; e < DM; e += 256) {
        const float* w = W + e * 64;
        float acc = bias[e];
#pragma unroll 16
        for (int i = 0; i < 64; i++) acc = fmaf(w[i], xs[i], acc);
        g_h[tok * DM + e] = acc;
    }
}

// ---------------- fused residual + layernorm (+ bf16 hi/lo out) ----------------
__global__ void resln_kernel(const float* __restrict__ src, float* __restrict__ res,
                             float* __restrict__ outf, __nv_bfloat16* __restrict__ ohi,
                             __nv_bfloat16* __restrict__ olo,
                             const float* __restrict__ w, const float* __restrict__ b, int add) {
    __shared__ float red1[8], red2[8];
    int base = blockIdx.x * DM;
    int tid = threadIdx.x;
    float v0 = src[base + tid];
    float v1 = src[base + tid + 256];
    float v2 = src[base + tid + 512];
    if (add) {
        v0 += res[base + tid];
        v1 += res[base + tid + 256];
        v2 += res[base + tid + 512];
    }
    res[base + tid]       = v0;
    res[base + tid + 256] = v1;
    res[base + tid + 512] = v2;

    float s = v0 + v1 + v2;
#pragma unroll
    for (int o = 16; o; o >>= 1) s += __shfl_xor_sync(0xffffffffu, s, o);
    if ((tid & 31) == 0) red1[tid >> 5] = s;
    __syncthreads();
    float tot = 0.f;
#pragma unroll
    for (int i = 0; i < 8; i++) tot += red1[i];
    float mean = tot * (1.f / DM);

    float d0 = v0 - mean, d1 = v1 - mean, d2 = v2 - mean;
    float sq = d0 * d0 + d1 * d1 + d2 * d2;
#pragma unroll
    for (int o = 16; o; o >>= 1) sq += __shfl_xor_sync(0xffffffffu, sq, o);
    if ((tid & 31) == 0) red2[tid >> 5] = sq;
    __syncthreads();
    float vt = 0.f;
#pragma unroll
    for (int i = 0; i < 8; i++) vt += red2[i];
    float inv = rsqrtf(vt * (1.f / DM) + 1e-5f);

    float o0 = d0 * inv * w[tid]       + b[tid];
    float o1 = d1 * inv * w[tid + 256] + b[tid + 256];
    float o2 = d2 * inv * w[tid + 512] + b[tid + 512];
    if (outf) {
        outf[base + tid]       = o0;
        outf[base + tid + 256] = o1;
        outf[base + tid + 512] = o2;
    } else {
        __nv_bfloat16 h0 = __float2bfloat16(o0), h1 = __float2bfloat16(o1), h2 = __float2bfloat16(o2);
        ohi[base + tid]       = h0;  olo[base + tid]       = __float2bfloat16(o0 - __bfloat162float(h0));
        ohi[base + tid + 256] = h1;  olo[base + tid + 256] = __float2bfloat16(o1 - __bfloat162float(h1));
        ohi[base + tid + 512] = h2;  olo[base + tid + 512] = __float2bfloat16(o2 - __bfloat162float(h2));
    }
}

// ---------------- SIMT SGEMM (x_proj / dt_proj) ----------------
#define BK 16
#define SPAD 4
enum { EPI_STORE = 0, EPI_SOFTPLUS = 1, EPI_TRANS = 2, EPI_XPROJ = 3 };

template <int BM, int BN, int TM, int TN, bool BNT, int EPI>
__device__ __forceinline__ void sgemm_body(
    const float* __restrict__ A, const float* __restrict__ B, float* __restrict__ C,
    int M, int N, int K, const float* __restrict__ bias,
    float* __restrict__ aux1, float* __restrict__ aux2) {
    constexpr int AE = BM * BK / 256;
    constexpr int BE = BN * BK / 256;
    __shared__ float As[BK][BM + SPAD];
    __shared__ float Bs[BK][BN + SPAD];

    int tid = threadIdx.x;
    int bm = blockIdx.y * BM;
    int bn = blockIdx.x * BN;
    int tx = tid % (BN / TN);
    int ty = tid / (BN / TN);

    float acc[TM][TN];
#pragma unroll
    for (int i = 0; i < TM; i++)
#pragma unroll
        for (int j = 0; j < TN; j++) acc[i][j] = 0.f;

    float pa[AE], pb[BE];
    auto loadA = [&](int k0) {
#pragma unroll
        for (int e = 0; e < AE; e++) {
            int i = tid + e * 256;
            int r = i / BK, kk = i % BK;
            int m = bm + r;
            pa[e] = (m < M) ? A[(long)m * K + k0 + kk] : 0.f;
        }
    };
    auto loadB = [&](int k0) {
#pragma unroll
        for (int e = 0; e < BE; e++) {
            int i = tid + e * 256;
            if (BNT) {
                int r = i / BK, kk = i % BK;
                pb[e] = B[(long)(bn + r) * K + k0 + kk];
            } else {
                int kk = i / BN, c = i % BN;
                pb[e] = B[(long)(k0 + kk) * N + bn + c];
            }
        }
    };
    auto storeAB = [&]() {
#pragma unroll
        for (int e = 0; e < AE; e++) {
            int i = tid + e * 256;
            As[i % BK][i / BK] = pa[e];
        }
#pragma unroll
        for (int e = 0; e < BE; e++) {
            int i = tid + e * 256;
            if (BNT) Bs[i % BK][i / BK] = pb[e];
            else     Bs[i / BN][i % BN] = pb[e];
        }
    };

    int KT = K / BK;
    loadA(0); loadB(0);
    storeAB();
    __syncthreads();

    for (int kt = 0; kt < KT; kt++) {
        if (kt + 1 < KT) { loadA((kt + 1) * BK); loadB((kt + 1) * BK); }
#pragma unroll
        for (int kk = 0; kk < BK; kk++) {
            float a[TM], bf[TN];
#pragma unroll
            for (int i = 0; i < TM; i++) a[i] = As[kk][ty * TM + i];
#pragma unroll
            for (int j = 0; j < TN; j++) bf[j] = Bs[kk][tx * TN + j];
#pragma unroll
            for (int i = 0; i < TM; i++)
#pragma unroll
                for (int j = 0; j < TN; j++) acc[i][j] = fmaf(a[i], bf[j], acc[i][j]);
        }
        __syncthreads();
        if (kt + 1 < KT) {
            storeAB();
            __syncthreads();
        }
    }

#pragma unroll
    for (int i = 0; i < TM; i++) {
        int m = bm + ty * TM + i;
        if (m >= M) continue;
#pragma unroll
        for (int j = 0; j < TN; j++) {
            int n = bn + tx * TN + j;
            float v = acc[i][j];
            if (EPI == EPI_STORE) {
                C[(long)m * N + n] = v;
            } else if (EPI == EPI_SOFTPLUS) {
                v += bias[m];
                C[(long)m * N + n] = (v > 20.f) ? v : log1pf(expf(v));
            } else if (EPI == EPI_TRANS) {
                C[(long)n * M + m] = v;
            } else {
                if (m < DTR)            C[(long)m * N + n] = v;
                else if (m < DTR + DS)  aux1[(long)n * DS + (m - DTR)] = v;
                else                    aux2[(long)n * DS + (m - DTR - DS)] = v;
            }
        }
    }
}

__global__ void __launch_bounds__(256, 2) sgemm_xproj(
    const float* __restrict__ A, const float* __restrict__ B, float* __restrict__ C,
    int M, int N, int K, float* __restrict__ aux1, float* __restrict__ aux2) {
    sgemm_body<32, 128, 2, 8, false, EPI_XPROJ>(A, B, C, M, N, K, nullptr, aux1, aux2);
}
__global__ void __launch_bounds__(256, 2) sgemm_dtproj(
    const float* __restrict__ A, const float* __restrict__ B, float* __restrict__ C,
    int M, int N, int K, const float* __restrict__ bias) {
    sgemm_body<128, 128, 8, 8, false, EPI_SOFTPLUS>(A, B, C, M, N, K, bias, nullptr, nullptr);
}

// ---------------- depthwise causal conv1d + bias + SiLU ----------------
__global__ void conv_silu_kernel(const float* __restrict__ cw, const float* __restrict__ cb) {
    int idx = blockIdx.x * 256 + threadIdx.x;
    if (idx >= DI * BLTOK) return;
    int d = idx >> 13;
    int bl = idx & 8191;
    int l = bl & 4095;
    const float* xp = g_xz + (long)d * BLTOK + bl;
    float w0 = cw[d * 4], w1 = cw[d * 4 + 1], w2 = cw[d * 4 + 2], w3 = cw[d * 4 + 3];
    float acc = cb[d];
    if (l >= 3) acc = fmaf(w0, xp[-3], acc);
    if (l >= 2) acc = fmaf(w1, xp[-2], acc);
    if (l >= 1) acc = fmaf(w2, xp[-1], acc);
    acc = fmaf(w3, xp[0], acc);
    float sg = 1.f / (1.f + __expf(-acc));
    g_xconv[idx] = acc * sg;
}

// ---------------- chunked selective scan: pass A (per-chunk P, Q) ----------------
// warp <-> (b, dp, chunk); lane: half = channel within pair, n = state index
__global__ void scanA_kernel(const float* __restrict__ A_log) {
    int g = blockIdx.x * (blockDim.x >> 5) + (threadIdx.x >> 5);
    int lane = threadIdx.x & 31;
    int c  = g % SCH;
    int dp = (g / SCH) % (DI / 2);
    int b  = g / (SCH * (DI / 2));
    int half = lane >> 4;
    int n = lane & 15;
    int d = dp * 2 + half;

    float Acoef = -expf(A_log[d * DS + n]);

    const float* dptr = g_delta + (size_t)d * BLTOK + b * L_SEQ + c * SCL;
    const float* uptr = g_xconv + (size_t)d * BLTOK + b * L_SEQ + c * SCL;
    const float* bptr = g_BcT + (size_t)(b * L_SEQ + c * SCL) * DS + n;

    float P = 1.f, s = 0.f;
#pragma unroll 8
    for (int t = 0; t < SCL; t++) {
        float de = dptr[t];
        float u  = uptr[t];
        float Bn = bptr[(size_t)t * DS];
        float dA = __expf(de * Acoef);
        P *= dA;
        s = fmaf(dA, s, de * u * Bn);
    }
    size_t o = (((size_t)b * SCH + c) * DI + d) * DS + n;
    g_P[o] = P;
    g_Q[o] = s;
}

// ---------------- pass B: combine chunk summaries -> per-chunk initial states ----------------
__global__ void scanB_kernel() {
    int g = blockIdx.x * (blockDim.x >> 5) + (threadIdx.x >> 5);
    int lane = threadIdx.x & 31;
    int dp = g % (DI / 2);
    int b  = g / (DI / 2);
    int half = lane >> 4;
    int n = lane & 15;
    int d = dp * 2 + half;

    float s = 0.f;
    size_t stride = (size_t)DI * DS;
    size_t o = (((size_t)b * SCH) * DI + d) * DS + n;
#pragma unroll 4
    for (int c = 0; c < SCH; c++) {
        g_S0[o] = s;
        s = fmaf(g_P[o], s, g_Q[o]);
        o += stride;
    }
}

// ---------------- pass C: recompute with true initial state, emit y ----------------
__global__ void scanC_kernel(const float* __restrict__ A_log, const float* __restrict__ Dvec) {
    int g = blockIdx.x * (blockDim.x >> 5) + (threadIdx.x >> 5);
    int lane = threadIdx.x & 31;
    int c  = g % SCH;
    int dp = (g / SCH) % (DI / 2);
    int b  = g / (SCH * (DI / 2));
    int half = lane >> 4;
    int n = lane & 15;
    int d = dp * 2 + half;

    float Acoef = -expf(A_log[d * DS + n]);
    float Dv = Dvec[d];

    const float* dptr = g_delta + (size_t)d * BLTOK + b * L_SEQ + c * SCL;
    const float* uptr = g_xconv + (size_t)d * BLTOK + b * L_SEQ + c * SCL;
    const float* zptr = g_xz + (size_t)(DI + d) * BLTOK + b * L_SEQ + c * SCL;
    const float* bptr = g_BcT + (size_t)(b * L_SEQ + c * SCL) * DS + n;
    const float* cptr = g_CcT + (size_t)(b * L_SEQ + c * SCL) * DS + n;
    float* yptr = g_y + (size_t)d * BLTOK + b * L_SEQ + c * SCL;

    float s = g_S0[(((size_t)b * SCH + c) * DI + d) * DS + n];
#pragma unroll 4
    for (int t = 0; t < SCL; t++) {
        float de = dptr[t];
        float u  = uptr[t];
        float zv = zptr[t];
        float Bn = bptr[(size_t)t * DS];
        float Cn = cptr[(size_t)t * DS];
        float dA = __expf(de * Acoef);
        s = fmaf(dA, s, de * u * Bn);
        float p = s * Cn;
        p += __shfl_xor_sync(0xffffffffu, p, 8, 16);
        p += __shfl_xor_sync(0xffffffffu, p, 4, 16);
        p += __shfl_xor_sync(0xffffffffu, p, 2, 16);
        p += __shfl_xor_sync(0xffffffffu, p, 1, 16);
        float yv = fmaf(Dv, u, p);
        float sg = 1.f / (1.f + __expf(-zv));
        yv *= zv * sg;
        if (n == 0) yptr[t] = yv;
    }
}

// ---------------- host launcher ----------------
extern "C" void kernel_launch(void* const* d_in, const int* in_sizes, int n_in,
                              void* d_out, int out_size) {
    const float* x     = (const float*)d_in[0];
    const float* embW  = (const float*)d_in[1];
    const float* embB  = (const float*)d_in[2];
    const float* normw = (const float*)d_in[3];
    const float* normb = (const float*)d_in[4];
    const float* inW   = (const float*)d_in[5];
    const float* convw = (const float*)d_in[6];
    const float* convb = (const float*)d_in[7];
    const float* xpW   = (const float*)d_in[8];
    const float* dtW   = (const float*)d_in[9];
    const float* dtb   = (const float*)d_in[10];
    const float* Alog  = (const float*)d_in[11];
    const float* Dv    = (const float*)d_in[12];
    const float* outW  = (const float*)d_in[13];
    const float* nfw   = (const float*)d_in[14];
    const float* nfb   = (const float*)d_in[15];
    float* out = (float*)d_out;

    float *h, *res, *xz, *xconv, *dt, *BcT, *CcT, *delta, *y;
    __nv_bfloat16 *winh, *winl, *wouth, *woutl, *hnh, *hnl, *yh, *yl;
    cudaGetSymbolAddress((void**)&h,     g_h);
    cudaGetSymbolAddress((void**)&res,   g_res);
    cudaGetSymbolAddress((void**)&xz,    g_xz);
    cudaGetSymbolAddress((void**)&xconv, g_xconv);
    cudaGetSymbolAddress((void**)&dt,    g_dt);
    cudaGetSymbolAddress((void**)&BcT,   g_BcT);
    cudaGetSymbolAddress((void**)&CcT,   g_CcT);
    cudaGetSymbolAddress((void**)&delta, g_delta);
    cudaGetSymbolAddress((void**)&y,     g_y);
    cudaGetSymbolAddress((void**)&winh,  g_WinHi);
    cudaGetSymbolAddress((void**)&winl,  g_WinLo);
    cudaGetSymbolAddress((void**)&wouth, g_WoutHi);
    cudaGetSymbolAddress((void**)&woutl, g_WoutLo);
    cudaGetSymbolAddress((void**)&hnh,   g_hnHi);
    cudaGetSymbolAddress((void**)&hnl,   g_hnLo);
    cudaGetSymbolAddress((void**)&yh,    g_yHi);
    cudaGetSymbolAddress((void**)&yl,    g_yLo);

    cudaFuncSetAttribute(mma_gemm_a, cudaFuncAttributeMaxDynamicSharedMemorySize, MMASMEM);
    cudaFuncSetAttribute(mma_gemm_b, cudaFuncAttributeMaxDynamicSharedMemorySize, MMASMEM);

    const int SCAN_WARPS = NB * (DI / 2) * SCH;       // 98304
    const int SCANB_WARPS = NB * (DI / 2);            // 1536

    embed_kernel<<<BLTOK, 256>>>(x, embW, embB);                                   // 0
    cvt_all_kernel<<<(CVT_TOTAL + 255) / 256, 256>>>(inW, outW);                   // 1

    for (int lyr = 0; lyr < NLAYER; lyr++) {
        resln_kernel<<<BLTOK, 256>>>(h, res, nullptr, hnh, hnl,                    // 2
                                     normw + lyr * DM, normb + lyr * DM, lyr > 0 ? 1 : 0);
        mma_gemm_a<<<dim3(64, 24), 256, MMASMEM>>>(                                // 3 <- profiled
            winh + (size_t)lyr * NIN_W, winl + (size_t)lyr * NIN_W, hnh, hnl, xz, DM, BLTOK);
        conv_silu_kernel<<<(DI * BLTOK + 255) / 256, 256>>>(convw + lyr * DI * 4, convb + lyr * DI);
        sgemm_xproj<<<dim3(64, 3), 256>>>(
            xpW + (long)lyr * (DTR + 2 * DS) * DI, xconv, dt, DTR + 2 * DS, BLTOK, DI, BcT, CcT);
        sgemm_dtproj<<<dim3(64, 12), 256>>>(
            dtW + (long)lyr * DI * DTR, dt, delta, DI, BLTOK, DTR, dtb + lyr * DI);
        // chunked parallel scan
        scanA_kernel<<<SCAN_WARPS / 4, 128>>>(Alog + (long)lyr * DI * DS);
        scanB_kernel<<<SCANB_WARPS / 4, 128>>>();
        scanC_kernel<<<SCAN_WARPS / 4, 128>>>(Alog + (long)lyr * DI * DS, Dv + lyr * DI);
        tcvt_kernel<<<dim3(BLTOK / 32, DI / 32), 256>>>(y, yh, yl);
        mma_gemm_b<<<dim3(64, 6), 256, MMASMEM>>>(
            wouth + (size_t)lyr * NOUT_W, woutl + (size_t)lyr * NOUT_W, yh, yl, h, DI, DM);
    }

    resln_kernel<<<BLTOK, 256>>>(h, res, out, nullptr, nullptr, nfw, nfb, 1);
}